// round 3
// baseline (speedup 1.0000x reference)
#include <cuda_runtime.h>
#include <cstdint>
#include <cstddef>

#define BB 64
#define TT 512
#define AA 128
#define HH 512
#define G4 2048  // 4*H
#define NCTA 128

// ---------------- scratch (static device allocations; no cudaMalloc) ----------------
__device__ float g_pre[(size_t)TT * BB * G4];   // 256MB: pre-gates  [t][b][4H]
__device__ float g_hall[(size_t)TT * BB * HH];  // 64MB : h history  [t][b][H]
__device__ float g_h[2][BB * HH];               // double-buffered recurrent h
__device__ float g_wp[(size_t)BB * AA * HH];    // 16MB : W'[b] = w_out + w_out@M[b]

// grid barrier state (must return to initial values after the kernel: 512 flips -> even)
__device__ unsigned g_bar_count = 0;
__device__ volatile unsigned g_bar_sense = 0;

// ---------------- kernel 1: pre[t][b][row] = bias[row] + x[b][t] . w_ih[row] ----------------
__global__ __launch_bounds__(256) void k_pregates(const float* __restrict__ x,
                                                  const float* __restrict__ w_ih,
                                                  const float* __restrict__ b_ih,
                                                  const float* __restrict__ b_hh) {
    __shared__ float As[64][68];
    __shared__ float Bs[64][68];
    const int t  = blockIdx.y;
    const int n0 = blockIdx.x * 64;
    const int tid = threadIdx.x;
    const int tm = tid >> 4;
    const int tn = tid & 15;
    float acc[4][4] = {};

    for (int k0 = 0; k0 < AA; k0 += 64) {
#pragma unroll
        for (int i = 0; i < 4; i++) {
            int id = tid + i * 256;
            int r = id >> 4, c4 = (id & 15) << 2;
            *(float4*)&As[r][c4] = *(const float4*)&x[((size_t)r * TT + t) * AA + k0 + c4];
            *(float4*)&Bs[r][c4] = *(const float4*)&w_ih[(size_t)(n0 + r) * AA + k0 + c4];
        }
        __syncthreads();
#pragma unroll
        for (int k = 0; k < 64; k += 4) {
            float4 a[4], b[4];
#pragma unroll
            for (int i = 0; i < 4; i++) a[i] = *(const float4*)&As[tm * 4 + i][k];
#pragma unroll
            for (int j = 0; j < 4; j++) b[j] = *(const float4*)&Bs[tn * 4 + j][k];
#pragma unroll
            for (int i = 0; i < 4; i++)
#pragma unroll
                for (int j = 0; j < 4; j++)
                    acc[i][j] += a[i].x * b[j].x + a[i].y * b[j].y + a[i].z * b[j].z + a[i].w * b[j].w;
        }
        __syncthreads();
    }
    float4 bi = *(const float4*)&b_ih[n0 + tn * 4];
    float4 bh = *(const float4*)&b_hh[n0 + tn * 4];
    float4 bias = make_float4(bi.x + bh.x, bi.y + bh.y, bi.z + bh.z, bi.w + bh.w);
#pragma unroll
    for (int i = 0; i < 4; i++) {
        int m = tm * 4 + i;
        float4 v = make_float4(acc[i][0] + bias.x, acc[i][1] + bias.y,
                               acc[i][2] + bias.z, acc[i][3] + bias.w);
        *(float4*)&g_pre[((size_t)t * BB + m) * G4 + n0 + tn * 4] = v;
    }
}

// ---------------- kernel 2: W'[b] = w_out + w_out @ M[b] ----------------
__global__ __launch_bounds__(256) void k_wprime(const float* __restrict__ w_out,
                                                const float* __restrict__ Mm) {
    __shared__ float As[64][68];
    __shared__ float Bs[64][68];
    const int b  = blockIdx.z;
    const int m0 = blockIdx.y * 64;
    const int n0 = blockIdx.x * 64;
    const int tid = threadIdx.x;
    const int tm = tid >> 4, tn = tid & 15;
    float acc[4][4] = {};

    for (int k0 = 0; k0 < HH; k0 += 64) {
#pragma unroll
        for (int i = 0; i < 4; i++) {
            int id = tid + i * 256;
            int r = id >> 4, c4 = (id & 15) << 2;
            *(float4*)&As[r][c4] = *(const float4*)&w_out[(size_t)(m0 + r) * HH + k0 + c4];
            *(float4*)&Bs[r][c4] = *(const float4*)&Mm[((size_t)b * HH + k0 + r) * HH + n0 + c4];
        }
        __syncthreads();
#pragma unroll
        for (int k = 0; k < 64; k += 4) {
            float4 a[4];
#pragma unroll
            for (int i = 0; i < 4; i++) a[i] = *(const float4*)&As[tm * 4 + i][k];
#pragma unroll
            for (int kk = 0; kk < 4; kk++) {
                float4 bv = *(const float4*)&Bs[k + kk][tn * 4];
#pragma unroll
                for (int i = 0; i < 4; i++) {
                    float av = (kk == 0) ? a[i].x : (kk == 1) ? a[i].y : (kk == 2) ? a[i].z : a[i].w;
                    acc[i][0] += av * bv.x; acc[i][1] += av * bv.y;
                    acc[i][2] += av * bv.z; acc[i][3] += av * bv.w;
                }
            }
        }
        __syncthreads();
    }
#pragma unroll
    for (int i = 0; i < 4; i++) {
        int m = m0 + tm * 4 + i;
        float4 w0 = *(const float4*)&w_out[(size_t)m * HH + n0 + tn * 4];
        float4 v = make_float4(acc[i][0] + w0.x, acc[i][1] + w0.y,
                               acc[i][2] + w0.z, acc[i][3] + w0.w);
        *(float4*)&g_wp[((size_t)b * AA + m) * HH + n0 + tn * 4] = v;
    }
}

// ---------------- kernel 3: persistent recurrent loop ----------------
// 128 CTAs x 256 threads. CTA owns 4 hidden units (j0..j0+3) x 4 gates = 16 w_hh rows,
// held resident in smem for all 512 steps. h staged per-step in transposed smem
// (hs[k][b] -> conflict-free LDS.32). Cell state c lives in a register.
// Grid-wide sense-reversing barrier between steps.
__global__ __launch_bounds__(256) void k_loop(const float* __restrict__ w_hh,
                                              const float* __restrict__ h0,
                                              const float* __restrict__ c0,
                                              const float* __restrict__ pre_base) {
    extern __shared__ float smem[];
    float* ws   = smem;                 // [16][512]
    float* hs   = smem + 16 * 512;      // [2][64][64]  (hs[buf][k][b])
    float* gbuf = smem + 16 * 512 + 2 * 64 * 64;  // [64][17]

    const int j0  = blockIdx.x * 4;
    const int tid = threadIdx.x;
    const int tm  = tid & 31;          // b in {tm, tm+32}
    const int tn2 = (tid >> 5) * 2;    // rows {tn2, tn2+1} of this CTA's 16

    // ---- load 16 w_hh rows into resident smem (once) ----
    {
        int r = tid >> 4;              // 0..15
        int c = (tid & 15) * 4;        // 0..60
        int g = r >> 2, jj = r & 3;
        const float* src = &w_hh[((size_t)(g * HH + j0 + jj)) * HH];
#pragma unroll
        for (int j = 0; j < 8; j++)
            *(float4*)&ws[r * 512 + c + j * 64] = *(const float4*)&src[c + j * 64];
    }

    // ---- pointwise-ownership mapping & cell state in register ----
    const int pb  = tid & 63;          // batch for pointwise
    const int pjj = tid >> 6;          // hidden unit 0..3 for pointwise
    const int pidx = pb * HH + j0 + pjj;
    float c_reg = c0[pidx];

    // ---- staging mapping ----
    const int sb = tid & 63;           // batch this thread stages
    const int sk = (tid >> 6) * 16;    // k-offset within 64-chunk (16 k's per thread)

    unsigned sense = 0;
    __syncthreads();

    for (int t = 0; t < TT; ++t) {
        const float* hsrc = (t == 0) ? h0 : g_h[t & 1];
        const float* pre_t = pre_base + (size_t)t * BB * G4;

        // stage chunk 0 (transposed)
        {
            const float* row = &hsrc[sb * HH];
#pragma unroll
            for (int j = 0; j < 4; j++) {
                float4 v = __ldcg((const float4*)&row[sk + j * 4]);
                float* d = &hs[0 * 4096 + (sk + j * 4) * 64 + sb];
                d[0] = v.x; d[64] = v.y; d[128] = v.z; d[192] = v.w;
            }
        }
        __syncthreads();

        float acc00 = 0.f, acc01 = 0.f, acc10 = 0.f, acc11 = 0.f;
#pragma unroll 1
        for (int c = 0; c < 8; ++c) {
            float4 pf[4];
            if (c < 7) {
                const float* row = &hsrc[sb * HH + (c + 1) * 64];
#pragma unroll
                for (int j = 0; j < 4; j++)
                    pf[j] = __ldcg((const float4*)&row[sk + j * 4]);
            }
            const float* hb = &hs[(c & 1) * 4096];
            const float* w0p = &ws[tn2 * 512 + c * 64];
            const float* w1p = &ws[(tn2 + 1) * 512 + c * 64];
#pragma unroll
            for (int k = 0; k < 64; k += 4) {
                float4 w0 = *(const float4*)&w0p[k];
                float4 w1 = *(const float4*)&w1p[k];
                float h00 = hb[(k + 0) * 64 + tm];
                float h01 = hb[(k + 1) * 64 + tm];
                float h02 = hb[(k + 2) * 64 + tm];
                float h03 = hb[(k + 3) * 64 + tm];
                float h10 = hb[(k + 0) * 64 + tm + 32];
                float h11 = hb[(k + 1) * 64 + tm + 32];
                float h12 = hb[(k + 2) * 64 + tm + 32];
                float h13 = hb[(k + 3) * 64 + tm + 32];
                acc00 += h00 * w0.x + h01 * w0.y + h02 * w0.z + h03 * w0.w;
                acc01 += h00 * w1.x + h01 * w1.y + h02 * w1.z + h03 * w1.w;
                acc10 += h10 * w0.x + h11 * w0.y + h12 * w0.z + h13 * w0.w;
                acc11 += h10 * w1.x + h11 * w1.y + h12 * w1.z + h13 * w1.w;
            }
            if (c < 7) {
                float* d = &hs[((c + 1) & 1) * 4096 + sk * 64 + sb];
#pragma unroll
                for (int j = 0; j < 4; j++) {
                    d[(j * 4 + 0) * 64] = pf[j].x;
                    d[(j * 4 + 1) * 64] = pf[j].y;
                    d[(j * 4 + 2) * 64] = pf[j].z;
                    d[(j * 4 + 3) * 64] = pf[j].w;
                }
            }
            __syncthreads();
        }

        // add precomputed input projection + bias into gate buffer
        {
            int g0 = tn2 >> 2, jj0 = tn2 & 3;
            int g1 = (tn2 + 1) >> 2, jj1 = (tn2 + 1) & 3;
            int row0 = g0 * HH + j0 + jj0;
            int row1 = g1 * HH + j0 + jj1;
            gbuf[tm * 17 + tn2]            = acc00 + __ldg(&pre_t[(size_t)tm * G4 + row0]);
            gbuf[tm * 17 + tn2 + 1]        = acc01 + __ldg(&pre_t[(size_t)tm * G4 + row1]);
            gbuf[(tm + 32) * 17 + tn2]     = acc10 + __ldg(&pre_t[(size_t)(tm + 32) * G4 + row0]);
            gbuf[(tm + 32) * 17 + tn2 + 1] = acc11 + __ldg(&pre_t[(size_t)(tm + 32) * G4 + row1]);
        }
        __syncthreads();

        // LSTM pointwise (thread owns (pb, pjj); c in register)
        {
            float xi = gbuf[pb * 17 + pjj];
            float xf = gbuf[pb * 17 + 4 + pjj];
            float xg = gbuf[pb * 17 + 8 + pjj];
            float xo = gbuf[pb * 17 + 12 + pjj];
            float si = 1.0f / (1.0f + __expf(-xi));
            float sf = 1.0f / (1.0f + __expf(-xf));
            float so = 1.0f / (1.0f + __expf(-xo));
            float tg = tanhf(xg);
            c_reg = sf * c_reg + si * tg;
            float hn = so * tanhf(c_reg);
            __stcg(&g_h[(t + 1) & 1][pidx], hn);
            g_hall[(size_t)t * BB * HH + pidx] = hn;
        }

        // ---- grid barrier (sense-reversing) ----
        __threadfence();
        __syncthreads();
        sense ^= 1u;
        if (tid == 0) {
            unsigned arrived = atomicAdd(&g_bar_count, 1u);
            if (arrived == NCTA - 1) {
                g_bar_count = 0;
                __threadfence();
                g_bar_sense = sense;
            } else {
                while (g_bar_sense != sense) { }
            }
            __threadfence();
        }
        __syncthreads();
    }
}

// ---------------- kernel 4: out[b][t][a] = h_all[t][b] . W'[b][a] + b_out[a] ----------
__global__ __launch_bounds__(256) void k_out(const float* __restrict__ b_out,
                                             float* __restrict__ out) {
    __shared__ float As[64][68];
    __shared__ float Bs[64][68];
    const int b  = blockIdx.z;
    const int m0 = blockIdx.y * 64;
    const int n0 = blockIdx.x * 64;
    const int tid = threadIdx.x;
    const int tm = tid >> 4, tn = tid & 15;
    float acc[4][4] = {};

    for (int k0 = 0; k0 < HH; k0 += 64) {
#pragma unroll
        for (int i = 0; i < 4; i++) {
            int id = tid + i * 256;
            int r = id >> 4, c4 = (id & 15) << 2;
            *(float4*)&As[r][c4] = *(const float4*)&g_hall[((size_t)(m0 + r) * BB + b) * HH + k0 + c4];
            *(float4*)&Bs[r][c4] = *(const float4*)&g_wp[((size_t)b * AA + n0 + r) * HH + k0 + c4];
        }
        __syncthreads();
#pragma unroll
        for (int k = 0; k < 64; k += 4) {
            float4 a[4], bv[4];
#pragma unroll
            for (int i = 0; i < 4; i++) a[i] = *(const float4*)&As[tm * 4 + i][k];
#pragma unroll
            for (int j = 0; j < 4; j++) bv[j] = *(const float4*)&Bs[tn * 4 + j][k];
#pragma unroll
            for (int i = 0; i < 4; i++)
#pragma unroll
                for (int j = 0; j < 4; j++)
                    acc[i][j] += a[i].x * bv[j].x + a[i].y * bv[j].y + a[i].z * bv[j].z + a[i].w * bv[j].w;
        }
        __syncthreads();
    }
    float4 bo = *(const float4*)&b_out[n0 + tn * 4];
#pragma unroll
    for (int i = 0; i < 4; i++) {
        int m = m0 + tm * 4 + i;
        float4 v = make_float4(acc[i][0] + bo.x, acc[i][1] + bo.y,
                               acc[i][2] + bo.z, acc[i][3] + bo.w);
        *(float4*)&out[((size_t)b * TT + m) * AA + n0 + tn * 4] = v;
    }
}

// ---------------- launch ----------------
extern "C" void kernel_launch(void* const* d_in, const int* in_sizes, int n_in,
                              void* d_out, int out_size) {
    const float* x     = (const float*)d_in[0];
    const float* w_ih  = (const float*)d_in[1];
    const float* w_hh  = (const float*)d_in[2];
    const float* b_ih  = (const float*)d_in[3];
    const float* b_hh  = (const float*)d_in[4];
    const float* Mm    = (const float*)d_in[5];
    const float* w_out = (const float*)d_in[6];
    const float* b_out = (const float*)d_in[7];
    const float* h0    = (const float*)d_in[8];
    const float* c0    = (const float*)d_in[9];
    float* out = (float*)d_out;

    const int loop_smem = (16 * 512 + 2 * 64 * 64 + 64 * 17) * sizeof(float); // ~70 KB
    cudaFuncSetAttribute(k_loop, cudaFuncAttributeMaxDynamicSharedMemorySize, loop_smem);

    k_pregates<<<dim3(G4 / 64, TT), 256>>>(x, w_ih, b_ih, b_hh);
    k_wprime<<<dim3(HH / 64, AA / 64, BB), 256>>>(w_out, Mm);

    float* pre_base;
    cudaGetSymbolAddress((void**)&pre_base, g_pre);
    k_loop<<<NCTA, 256, loop_smem>>>(w_hh, h0, c0, pre_base);

    k_out<<<dim3(AA / 64, TT / 64, BB), 256>>>(b_out, out);
}